// round 1
// baseline (speedup 1.0000x reference)
#include <cuda_runtime.h>
#include <cmath>

#define BB 4
#define TT 4096
#define DD 1024
#define HH 64

// Scratch for projected q/k/v heads: 3 x 4 MB (allocation-free rule -> device globals)
__device__ float g_qh[BB*TT*HH];
__device__ float g_kh[BB*TT*HH];
__device__ float g_vh[BB*TT*HH];

#define PBK 32

// out[M,H] = X[M,D] @ W[D,H]; M = B*T; blockIdx.y selects (q,k,v)
__global__ __launch_bounds__(256) void proj_kernel(
    const float* __restrict__ q, const float* __restrict__ k, const float* __restrict__ v,
    const float* __restrict__ Wq, const float* __restrict__ Wk, const float* __restrict__ Wv)
{
    const float* X; const float* W; float* O;
    if (blockIdx.y == 0)      { X = q; W = Wq; O = g_qh; }
    else if (blockIdx.y == 1) { X = k; W = Wk; O = g_kh; }
    else                      { X = v; W = Wv; O = g_vh; }

    __shared__ float Xs[PBK][64 + 4];   // [k][m] transposed, padded
    __shared__ float Ws[PBK][HH + 4];   // [k][h] padded

    const int tid = threadIdx.x;
    const int mr  = (tid >> 4) << 2;    // 0,4,...,60
    const int hc  = (tid & 15) << 2;    // 0,4,...,60
    const int m0  = blockIdx.x * 64;

    float acc[4][4] = {};

    for (int k0 = 0; k0 < DD; k0 += PBK) {
        // stage X chunk [64 rows x 32 k], transposed into smem
        for (int i = tid; i < 64 * PBK / 4; i += 256) {
            int m  = i >> 3;            // PBK/4 = 8 float4 per row
            int k4 = (i & 7) << 2;
            float4 xv = *(const float4*)&X[(size_t)(m0 + m) * DD + k0 + k4];
            Xs[k4 + 0][m] = xv.x; Xs[k4 + 1][m] = xv.y;
            Xs[k4 + 2][m] = xv.z; Xs[k4 + 3][m] = xv.w;
        }
        // stage W chunk [32 k x 64 h]
        for (int i = tid; i < PBK * HH / 4; i += 256) {
            int kk = i >> 4;            // HH/4 = 16 float4 per row
            int h4 = (i & 15) << 2;
            *(float4*)&Ws[kk][h4] = *(const float4*)&W[(size_t)(k0 + kk) * HH + h4];
        }
        __syncthreads();

        #pragma unroll 8
        for (int kk = 0; kk < PBK; kk++) {
            float4 xv = *(const float4*)&Xs[kk][mr];
            float4 wv = *(const float4*)&Ws[kk][hc];
            float xf[4] = {xv.x, xv.y, xv.z, xv.w};
            float wf[4] = {wv.x, wv.y, wv.z, wv.w};
            #pragma unroll
            for (int i = 0; i < 4; i++)
                #pragma unroll
                for (int j = 0; j < 4; j++)
                    acc[i][j] = fmaf(xf[i], wf[j], acc[i][j]);
        }
        __syncthreads();
    }

    #pragma unroll
    for (int i = 0; i < 4; i++) {
        float4 o = make_float4(acc[i][0], acc[i][1], acc[i][2], acc[i][3]);
        *(float4*)&O[(size_t)(m0 + mr + i) * HH + hc] = o;
    }
}

// Flash attention, 64x64 tiles, online softmax, causal.
// grid: (T/64/2, B); each block handles query tiles x and 63-x (perfect balance: 65 key-tile units each).
__global__ __launch_bounds__(256) void attn_kernel(float* __restrict__ out)
{
    extern __shared__ float sm[];
    float* Qs  = sm;                 // [64 d][64 q] transposed
    float* Ks  = Qs + 64 * 64;       // [64 d][64 k] transposed
    float* Vs  = Ks + 64 * 64;       // [64 k][64 h]
    float* Ps  = Vs + 64 * 64;       // [64 q][65]   (pad 65 -> conflict-free row scans)
    float* m_s = Ps + 64 * 65;
    float* l_s = m_s + 64;
    float* sc_s = l_s + 64;

    const int b   = blockIdx.y;
    const int tid = threadIdx.x;
    const int qr  = (tid >> 4) << 2;   // query-row group
    const int cc  = (tid & 15) << 2;   // key-col / head-col group

    const float* qh = g_qh + (size_t)b * TT * HH;
    const float* kh = g_kh + (size_t)b * TT * HH;
    const float* vh = g_vh + (size_t)b * TT * HH;

    for (int half = 0; half < 2; half++) {
        const int qb = (half == 0) ? (int)blockIdx.x : (TT / 64 - 1 - (int)blockIdx.x);
        const int q0 = qb * 64;

        if (tid < 64) { m_s[tid] = -INFINITY; l_s[tid] = 0.0f; }
        float acc[4][4] = {};

        // load Q tile transposed: Qs[d][r]
        for (int i = tid; i < 64 * HH / 4; i += 256) {
            int r = i >> 4; int d4 = (i & 15) << 2;
            float4 qv = *(const float4*)&qh[(size_t)(q0 + r) * HH + d4];
            Qs[(d4 + 0) * 64 + r] = qv.x; Qs[(d4 + 1) * 64 + r] = qv.y;
            Qs[(d4 + 2) * 64 + r] = qv.z; Qs[(d4 + 3) * 64 + r] = qv.w;
        }
        __syncthreads();

        const int nkb = qb + 1;
        for (int kb = 0; kb < nkb; kb++) {
            const int k0 = kb * 64;
            for (int i = tid; i < 64 * HH / 4; i += 256) {
                int r = i >> 4; int d4 = (i & 15) << 2;
                float4 kv = *(const float4*)&kh[(size_t)(k0 + r) * HH + d4];
                Ks[(d4 + 0) * 64 + r] = kv.x; Ks[(d4 + 1) * 64 + r] = kv.y;
                Ks[(d4 + 2) * 64 + r] = kv.z; Ks[(d4 + 3) * 64 + r] = kv.w;
                float4 vv = *(const float4*)&vh[(size_t)(k0 + r) * HH + d4];
                *(float4*)&Vs[r * 64 + d4] = vv;
            }
            __syncthreads();

            // S = (Q K^T) / 8
            float sacc[4][4] = {};
            #pragma unroll 16
            for (int d = 0; d < HH; d++) {
                float4 qv = *(const float4*)&Qs[d * 64 + qr];
                float4 kv = *(const float4*)&Ks[d * 64 + cc];
                float qf[4] = {qv.x, qv.y, qv.z, qv.w};
                float kf[4] = {kv.x, kv.y, kv.z, kv.w};
                #pragma unroll
                for (int i = 0; i < 4; i++)
                    #pragma unroll
                    for (int j = 0; j < 4; j++)
                        sacc[i][j] = fmaf(qf[i], kf[j], sacc[i][j]);
            }
            const bool diag = (kb == nkb - 1);   // k0 == q0 on the last block
            #pragma unroll
            for (int i = 0; i < 4; i++)
                #pragma unroll
                for (int j = 0; j < 4; j++) {
                    float s = sacc[i][j] * 0.125f;
                    if (diag && (cc + j > qr + i)) s = -INFINITY;
                    Ps[(qr + i) * 65 + cc + j] = s;
                }
            __syncthreads();

            // online softmax: 4 threads per row
            {
                const int row = tid >> 2, part = tid & 3;
                const int c0 = part * 16;
                float tm = -INFINITY;
                #pragma unroll
                for (int c2 = 0; c2 < 16; c2++) tm = fmaxf(tm, Ps[row * 65 + c0 + c2]);
                tm = fmaxf(tm, __shfl_xor_sync(0xffffffffu, tm, 1));
                tm = fmaxf(tm, __shfl_xor_sync(0xffffffffu, tm, 2));
                const float m_old = m_s[row];
                const float m_new = fmaxf(m_old, tm);
                float ssum = 0.0f;
                #pragma unroll
                for (int c2 = 0; c2 < 16; c2++) {
                    float p = __expf(Ps[row * 65 + c0 + c2] - m_new);
                    Ps[row * 65 + c0 + c2] = p;
                    ssum += p;
                }
                ssum += __shfl_xor_sync(0xffffffffu, ssum, 1);
                ssum += __shfl_xor_sync(0xffffffffu, ssum, 2);
                if (part == 0) {
                    float corr = __expf(m_old - m_new);
                    l_s[row] = l_s[row] * corr + ssum;
                    m_s[row] = m_new;
                    sc_s[row] = corr;
                }
            }
            __syncthreads();

            // O = O*corr + P @ V
            #pragma unroll
            for (int i = 0; i < 4; i++) {
                float c = sc_s[qr + i];
                #pragma unroll
                for (int j = 0; j < 4; j++) acc[i][j] *= c;
            }
            #pragma unroll 8
            for (int kk = 0; kk < 64; kk++) {
                float4 vv = *(const float4*)&Vs[kk * 64 + cc];
                float vf[4] = {vv.x, vv.y, vv.z, vv.w};
                float pf[4];
                #pragma unroll
                for (int i = 0; i < 4; i++) pf[i] = Ps[(qr + i) * 65 + kk];
                #pragma unroll
                for (int i = 0; i < 4; i++)
                    #pragma unroll
                    for (int j = 0; j < 4; j++)
                        acc[i][j] = fmaf(pf[i], vf[j], acc[i][j]);
            }
            __syncthreads();
        }

        // epilogue: normalize and store
        #pragma unroll
        for (int i = 0; i < 4; i++) {
            float inv = 1.0f / l_s[qr + i];
            float4 o = make_float4(acc[i][0] * inv, acc[i][1] * inv,
                                   acc[i][2] * inv, acc[i][3] * inv);
            *(float4*)&out[((size_t)b * TT + q0 + qr + i) * HH + cc] = o;
        }
        __syncthreads();  // before next half reuses smem + m/l
    }
}

extern "C" void kernel_launch(void* const* d_in, const int* in_sizes, int n_in,
                              void* d_out, int out_size)
{
    const float* q  = (const float*)d_in[0];
    const float* k  = (const float*)d_in[1];
    const float* v  = (const float*)d_in[2];
    const float* Wq = (const float*)d_in[3];
    const float* Wk = (const float*)d_in[4];
    const float* Wv = (const float*)d_in[5];
    // d_in[6] is the tril mask: causality implemented analytically.

    proj_kernel<<<dim3(BB * TT / 64, 3), 256>>>(q, k, v, Wq, Wk, Wv);

    const int smem_bytes = (3 * 64 * 64 + 64 * 65 + 3 * 64) * (int)sizeof(float); // 66560
    cudaFuncSetAttribute(attn_kernel, cudaFuncAttributeMaxDynamicSharedMemorySize, smem_bytes);
    attn_kernel<<<dim3(TT / 64 / 2, BB), 256, smem_bytes>>>((float*)d_out);
}

// round 4
// speedup vs baseline: 1.4393x; 1.4393x over previous
#include <cuda_runtime.h>
#include <cuda_bf16.h>
#include <cstdint>

#define BB 4
#define TT 4096
#define DD 1024
#define HH 64
#define NT (BB*TT)

#define NEGINF __int_as_float(0xff800000)

// bf16 hi/lo projected tensors (12 MB static scratch)
__device__ __nv_bfloat16 g_qh_hi[NT*HH], g_qh_lo[NT*HH];
__device__ __nv_bfloat16 g_kh_hi[NT*HH], g_kh_lo[NT*HH];
__device__ __nv_bfloat16 g_vt_hi[HH*NT], g_vt_lo[HH*NT];   // V transposed: [h][token]

// pack two floats -> bf16x2 (lo in low half, hi in high half)
__device__ __forceinline__ uint32_t pack2(float lo, float hi) {
    uint32_t r;
    asm("cvt.rn.bf16x2.f32 %0, %1, %2;" : "=r"(r) : "f"(hi), "f"(lo));
    return r;
}
// m16n8k16 row.col bf16 -> f32 accumulate in place
__device__ __forceinline__ void mma16816(float* d, uint32_t a0, uint32_t a1, uint32_t a2, uint32_t a3,
                                         uint32_t b0, uint32_t b1) {
    asm volatile("mma.sync.aligned.m16n8k16.row.col.f32.bf16.bf16.f32 "
        "{%0,%1,%2,%3}, {%4,%5,%6,%7}, {%8,%9}, {%0,%1,%2,%3};"
        : "+f"(d[0]), "+f"(d[1]), "+f"(d[2]), "+f"(d[3])
        : "r"(a0), "r"(a1), "r"(a2), "r"(a3), "r"(b0), "r"(b1));
}

// ======================= projection: [16384,1024] @ [1024,64] =======================
#define XPAD 36
__global__ __launch_bounds__(256) void proj_tc(
    const float* __restrict__ q, const float* __restrict__ k, const float* __restrict__ v,
    const float* __restrict__ Wq, const float* __restrict__ Wk, const float* __restrict__ Wv)
{
    __shared__ uint16_t Xh[128][XPAD], Xl[128][XPAD], Wh[64][XPAD], Wl[64][XPAD];
    const int tid = threadIdx.x, wid = tid >> 5, lane = tid & 31;
    const int g = lane >> 2, t4 = lane & 3;
    const int y = blockIdx.y;
    const float* X = (y == 0) ? q : (y == 1) ? k : v;
    const float* W = (y == 0) ? Wq : (y == 1) ? Wk : Wv;
    const int m0 = blockIdx.x * 128;

    float acc[8][4] = {};

    for (int c0 = 0; c0 < DD; c0 += 32) {
        __syncthreads();
        // X chunk [128 x 32] fp32 -> hi/lo bf16
        for (int i = tid; i < 1024; i += 256) {
            int r = i >> 3, c4 = (i & 7) << 2;
            float4 xv = *(const float4*)&X[(size_t)(m0 + r) * DD + c0 + c4];
            uint32_t h01 = pack2(xv.x, xv.y), h23 = pack2(xv.z, xv.w);
            float hx = __uint_as_float(h01 << 16), hy = __uint_as_float(h01 & 0xffff0000u);
            float hz = __uint_as_float(h23 << 16), hw = __uint_as_float(h23 & 0xffff0000u);
            uint32_t l01 = pack2(xv.x - hx, xv.y - hy), l23 = pack2(xv.z - hz, xv.w - hw);
            *(uint32_t*)&Xh[r][c4]     = h01; *(uint32_t*)&Xh[r][c4 + 2] = h23;
            *(uint32_t*)&Xl[r][c4]     = l01; *(uint32_t*)&Xl[r][c4 + 2] = l23;
        }
        // W chunk [32 x 64] -> Wt[n][k] hi/lo
        {
            int n = tid & 63, kb = (tid >> 6) << 3;
            float w[8];
            #pragma unroll
            for (int e = 0; e < 8; e++) w[e] = W[(size_t)(c0 + kb + e) * HH + n];
            #pragma unroll
            for (int e = 0; e < 4; e++) {
                uint32_t hp = pack2(w[2*e], w[2*e+1]);
                float h0 = __uint_as_float(hp << 16), h1 = __uint_as_float(hp & 0xffff0000u);
                uint32_t lp = pack2(w[2*e] - h0, w[2*e+1] - h1);
                *(uint32_t*)&Wh[n][kb + 2*e] = hp;
                *(uint32_t*)&Wl[n][kb + 2*e] = lp;
            }
        }
        __syncthreads();
        const int row = (wid << 4) + g;
        #pragma unroll
        for (int cs = 0; cs < 2; cs++) {
            const int kc = cs * 16 + 2 * t4;
            uint32_t ah0 = *(uint32_t*)&Xh[row][kc],     ah1 = *(uint32_t*)&Xh[row + 8][kc];
            uint32_t ah2 = *(uint32_t*)&Xh[row][kc + 8], ah3 = *(uint32_t*)&Xh[row + 8][kc + 8];
            uint32_t al0 = *(uint32_t*)&Xl[row][kc],     al1 = *(uint32_t*)&Xl[row + 8][kc];
            uint32_t al2 = *(uint32_t*)&Xl[row][kc + 8], al3 = *(uint32_t*)&Xl[row + 8][kc + 8];
            #pragma unroll
            for (int j = 0; j < 8; j++) {
                int n = 8 * j + g;
                uint32_t bh0 = *(uint32_t*)&Wh[n][kc], bh1 = *(uint32_t*)&Wh[n][kc + 8];
                uint32_t bl0 = *(uint32_t*)&Wl[n][kc], bl1 = *(uint32_t*)&Wl[n][kc + 8];
                mma16816(acc[j], ah0, ah1, ah2, ah3, bh0, bh1);
                mma16816(acc[j], ah0, ah1, ah2, ah3, bl0, bl1);
                mma16816(acc[j], al0, al1, al2, al3, bh0, bh1);
            }
        }
    }

    const int row0 = m0 + (wid << 4) + g;
    if (y < 2) {
        __nv_bfloat16* Oh = (y == 0) ? g_qh_hi : g_kh_hi;
        __nv_bfloat16* Ol = (y == 0) ? g_qh_lo : g_kh_lo;
        #pragma unroll
        for (int j = 0; j < 8; j++) {
            int col = 8 * j + 2 * t4;
            uint32_t hp0 = pack2(acc[j][0], acc[j][1]);
            float h0 = __uint_as_float(hp0 << 16), h1 = __uint_as_float(hp0 & 0xffff0000u);
            uint32_t lp0 = pack2(acc[j][0] - h0, acc[j][1] - h1);
            *(uint32_t*)&Oh[(size_t)row0 * HH + col] = hp0;
            *(uint32_t*)&Ol[(size_t)row0 * HH + col] = lp0;
            uint32_t hp1 = pack2(acc[j][2], acc[j][3]);
            float h2 = __uint_as_float(hp1 << 16), h3 = __uint_as_float(hp1 & 0xffff0000u);
            uint32_t lp1 = pack2(acc[j][2] - h2, acc[j][3] - h3);
            *(uint32_t*)&Oh[(size_t)(row0 + 8) * HH + col] = hp1;
            *(uint32_t*)&Ol[(size_t)(row0 + 8) * HH + col] = lp1;
        }
    } else {
        // V: store transposed [h][token] hi/lo (scatter bf16 stores)
        #pragma unroll
        for (int j = 0; j < 8; j++) {
            int h = 8 * j + 2 * t4;
            #pragma unroll
            for (int e = 0; e < 4; e++) {
                int hc = h + (e & 1);
                int rr = row0 + ((e >= 2) ? 8 : 0);
                float val = acc[j][e];
                __nv_bfloat16 bh = __float2bfloat16(val);
                float res = val - __bfloat162float(bh);
                g_vt_hi[(size_t)hc * NT + rr] = bh;
                g_vt_lo[(size_t)hc * NT + rr] = __float2bfloat16(res);
            }
        }
    }
}

// ======================= flash attention: mma.sync, BM=128, BN=64 =======================
// dynamic smem layout (uint16 elems, 68-col padded rows):
// Qh[128][68] @0, Ql @8704, Kh[64][68] @17408, Kl @21760, Vh @26112, Vl @30464 -> 69632 bytes
__global__ __launch_bounds__(256, 1) void attn_tc(float* __restrict__ out)
{
    extern __shared__ uint16_t sm[];
    uint16_t* Qh = sm;            uint16_t* Ql = sm + 8704;
    uint16_t* Kh = sm + 17408;    uint16_t* Kl = sm + 21760;
    uint16_t* Vh = sm + 26112;    uint16_t* Vl = sm + 30464;
    const int tid = threadIdx.x, wid = tid >> 5, lane = tid & 31;
    const int g = lane >> 2, t4 = lane & 3;
    const int b = blockIdx.y, qb = blockIdx.x;
    const int q0 = qb * 128, bT = b * TT;
    const int rowA = (wid << 4) + g;

    // load Q tile hi/lo
    for (int i = tid; i < 2048; i += 256) {
        int r = i >> 4, c4 = (i & 15) << 2;
        *(uint2*)&Qh[r * 68 + c4] = *(const uint2*)&g_qh_hi[(size_t)(bT + q0 + r) * HH + c4];
        *(uint2*)&Ql[r * 68 + c4] = *(const uint2*)&g_qh_lo[(size_t)(bT + q0 + r) * HH + c4];
    }

    float oacc[8][4] = {};
    float m0r = NEGINF, m1r = NEGINF, l0r = 0.0f, l1r = 0.0f;
    const int ntiles = 2 * qb + 2;

    for (int tt = 0; tt < ntiles; tt++) {
        const int k0 = tt * 64;
        __syncthreads();
        for (int i = tid; i < 1024; i += 256) {
            int r = i >> 4, c4 = (i & 15) << 2;
            *(uint2*)&Kh[r * 68 + c4] = *(const uint2*)&g_kh_hi[(size_t)(bT + k0 + r) * HH + c4];
            *(uint2*)&Kl[r * 68 + c4] = *(const uint2*)&g_kh_lo[(size_t)(bT + k0 + r) * HH + c4];
            *(uint2*)&Vh[r * 68 + c4] = *(const uint2*)&g_vt_hi[(size_t)r * NT + bT + k0 + c4];
            *(uint2*)&Vl[r * 68 + c4] = *(const uint2*)&g_vt_lo[(size_t)r * NT + bT + k0 + c4];
        }
        __syncthreads();

        // S = Q K^T (3 split terms)
        float sacc[8][4] = {};
        #pragma unroll
        for (int c = 0; c < 4; c++) {
            const int kc = 16 * c + 2 * t4;
            uint32_t ah0 = *(uint32_t*)&Qh[rowA * 68 + kc],       ah1 = *(uint32_t*)&Qh[(rowA + 8) * 68 + kc];
            uint32_t ah2 = *(uint32_t*)&Qh[rowA * 68 + kc + 8],   ah3 = *(uint32_t*)&Qh[(rowA + 8) * 68 + kc + 8];
            uint32_t al0 = *(uint32_t*)&Ql[rowA * 68 + kc],       al1 = *(uint32_t*)&Ql[(rowA + 8) * 68 + kc];
            uint32_t al2 = *(uint32_t*)&Ql[rowA * 68 + kc + 8],   al3 = *(uint32_t*)&Ql[(rowA + 8) * 68 + kc + 8];
            #pragma unroll
            for (int j = 0; j < 8; j++) {
                int n = 8 * j + g;
                uint32_t bh0 = *(uint32_t*)&Kh[n * 68 + kc], bh1 = *(uint32_t*)&Kh[n * 68 + kc + 8];
                uint32_t bl0 = *(uint32_t*)&Kl[n * 68 + kc], bl1 = *(uint32_t*)&Kl[n * 68 + kc + 8];
                mma16816(sacc[j], ah0, ah1, ah2, ah3, bh0, bh1);
                mma16816(sacc[j], ah0, ah1, ah2, ah3, bl0, bl1);
                mma16816(sacc[j], al0, al1, al2, al3, bh0, bh1);
            }
        }

        // scale + causal mask (only last two tiles can touch the diagonal)
        const bool domask = (tt >= ntiles - 2);
        #pragma unroll
        for (int j = 0; j < 8; j++) {
            int col = k0 + 8 * j + 2 * t4;
            #pragma unroll
            for (int e = 0; e < 4; e++) {
                float val = sacc[j][e] * 0.125f;
                if (domask) {
                    int rr = q0 + rowA + ((e >= 2) ? 8 : 0);
                    if (col + (e & 1) > rr) val = NEGINF;
                }
                sacc[j][e] = val;
            }
        }

        // online softmax (rows g and g+8; cols spread over the 4-lane quad)
        float mx0 = NEGINF, mx1 = NEGINF;
        #pragma unroll
        for (int j = 0; j < 8; j++) {
            mx0 = fmaxf(mx0, fmaxf(sacc[j][0], sacc[j][1]));
            mx1 = fmaxf(mx1, fmaxf(sacc[j][2], sacc[j][3]));
        }
        mx0 = fmaxf(mx0, __shfl_xor_sync(0xffffffffu, mx0, 1));
        mx0 = fmaxf(mx0, __shfl_xor_sync(0xffffffffu, mx0, 2));
        mx1 = fmaxf(mx1, __shfl_xor_sync(0xffffffffu, mx1, 1));
        mx1 = fmaxf(mx1, __shfl_xor_sync(0xffffffffu, mx1, 2));
        const float mn0 = fmaxf(m0r, mx0), mn1 = fmaxf(m1r, mx1);
        const float corr0 = __expf(m0r - mn0), corr1 = __expf(m1r - mn1);
        float s0 = 0.0f, s1 = 0.0f;
        #pragma unroll
        for (int j = 0; j < 8; j++) {
            float p0 = __expf(sacc[j][0] - mn0), p1 = __expf(sacc[j][1] - mn0);
            float p2 = __expf(sacc[j][2] - mn1), p3 = __expf(sacc[j][3] - mn1);
            sacc[j][0] = p0; sacc[j][1] = p1; sacc[j][2] = p2; sacc[j][3] = p3;
            s0 += p0 + p1; s1 += p2 + p3;
        }
        s0 += __shfl_xor_sync(0xffffffffu, s0, 1);
        s0 += __shfl_xor_sync(0xffffffffu, s0, 2);
        s1 += __shfl_xor_sync(0xffffffffu, s1, 1);
        s1 += __shfl_xor_sync(0xffffffffu, s1, 2);
        l0r = l0r * corr0 + s0; l1r = l1r * corr1 + s1;
        m0r = mn0; m1r = mn1;

        // rescale O accumulator
        #pragma unroll
        for (int j = 0; j < 8; j++) {
            oacc[j][0] *= corr0; oacc[j][1] *= corr0;
            oacc[j][2] *= corr1; oacc[j][3] *= corr1;
        }

        // O += P V  (P stays in registers: S accumulator layout == A fragment layout)
        #pragma unroll
        for (int c = 0; c < 4; c++) {
            uint32_t ph0 = pack2(sacc[2*c][0],   sacc[2*c][1]);
            uint32_t ph1 = pack2(sacc[2*c][2],   sacc[2*c][3]);
            uint32_t ph2 = pack2(sacc[2*c+1][0], sacc[2*c+1][1]);
            uint32_t ph3 = pack2(sacc[2*c+1][2], sacc[2*c+1][3]);
            float r0 = sacc[2*c][0]   - __uint_as_float(ph0 << 16);
            float r1 = sacc[2*c][1]   - __uint_as_float(ph0 & 0xffff0000u);
            float r2 = sacc[2*c][2]   - __uint_as_float(ph1 << 16);
            float r3 = sacc[2*c][3]   - __uint_as_float(ph1 & 0xffff0000u);
            float r4 = sacc[2*c+1][0] - __uint_as_float(ph2 << 16);
            float r5 = sacc[2*c+1][1] - __uint_as_float(ph2 & 0xffff0000u);
            float r6 = sacc[2*c+1][2] - __uint_as_float(ph3 << 16);
            float r7 = sacc[2*c+1][3] - __uint_as_float(ph3 & 0xffff0000u);
            uint32_t pl0 = pack2(r0, r1), pl1 = pack2(r2, r3);
            uint32_t pl2 = pack2(r4, r5), pl3 = pack2(r6, r7);
            const int kc = 16 * c + 2 * t4;
            #pragma unroll
            for (int j2 = 0; j2 < 8; j2++) {
                int n = 8 * j2 + g;
                uint32_t bh0 = *(uint32_t*)&Vh[n * 68 + kc], bh1 = *(uint32_t*)&Vh[n * 68 + kc + 8];
                uint32_t bl0 = *(uint32_t*)&Vl[n * 68 + kc], bl1 = *(uint32_t*)&Vl[n * 68 + kc + 8];
                mma16816(oacc[j2], ph0, ph1, ph2, ph3, bh0, bh1);
                mma16816(oacc[j2], ph0, ph1, ph2, ph3, bl0, bl1);
                mma16816(oacc[j2], pl0, pl1, pl2, pl3, bh0, bh1);
            }
        }
    }

    const float inv0 = 1.0f / l0r, inv1 = 1.0f / l1r;
    #pragma unroll
    for (int j = 0; j < 8; j++) {
        int col = 8 * j + 2 * t4;
        *(float2*)&out[(size_t)(bT + q0 + rowA) * HH + col] =
            make_float2(oacc[j][0] * inv0, oacc[j][1] * inv0);
        *(float2*)&out[(size_t)(bT + q0 + rowA + 8) * HH + col] =
            make_float2(oacc[j][2] * inv1, oacc[j][3] * inv1);
    }
}

extern "C" void kernel_launch(void* const* d_in, const int* in_sizes, int n_in,
                              void* d_out, int out_size)
{
    const float* q  = (const float*)d_in[0];
    const float* k  = (const float*)d_in[1];
    const float* v  = (const float*)d_in[2];
    const float* Wq = (const float*)d_in[3];
    const float* Wk = (const float*)d_in[4];
    const float* Wv = (const float*)d_in[5];
    // d_in[6] (tril mask) implemented analytically

    proj_tc<<<dim3(NT / 128, 3), 256>>>(q, k, v, Wq, Wk, Wv);

    const int attn_smem = 69632;
    cudaFuncSetAttribute(attn_tc, cudaFuncAttributeMaxDynamicSharedMemorySize, attn_smem);
    attn_tc<<<dim3(TT / 128, BB), 256, attn_smem>>>((float*)d_out);
}

// round 7
// speedup vs baseline: 1.7747x; 1.2330x over previous
#include <cuda_runtime.h>
#include <cuda_bf16.h>
#include <cstdint>

#define BB 4
#define TT 4096
#define DD 1024
#define HH 64
#define NT (BB*TT)
#define NQB (TT/128)

#define NEGINF __int_as_float(0xff800000)
#define MFLOOR (-1e30f)

// bf16 hi/lo projected tensors (12 MB static scratch)
__device__ __nv_bfloat16 g_qh_hi[NT*HH], g_qh_lo[NT*HH];
__device__ __nv_bfloat16 g_kh_hi[NT*HH], g_kh_lo[NT*HH];
__device__ __nv_bfloat16 g_vt_hi[HH*NT], g_vt_lo[HH*NT];   // V transposed: [h][token]

// split-KV partials: unnormalized O + running max/sum per row
__device__ float g_po[2][NT*HH];
__device__ float g_pm[2][NT];
__device__ float g_pl[2][NT];

// pack two floats -> bf16x2 (lo in low half, hi in high half)
__device__ __forceinline__ uint32_t pack2(float lo, float hi) {
    uint32_t r;
    asm("cvt.rn.bf16x2.f32 %0, %1, %2;" : "=r"(r) : "f"(hi), "f"(lo));
    return r;
}
// m16n8k16 row.col bf16 -> f32 accumulate in place
__device__ __forceinline__ void mma16816(float* d, uint32_t a0, uint32_t a1, uint32_t a2, uint32_t a3,
                                         uint32_t b0, uint32_t b1) {
    asm volatile("mma.sync.aligned.m16n8k16.row.col.f32.bf16.bf16.f32 "
        "{%0,%1,%2,%3}, {%4,%5,%6,%7}, {%8,%9}, {%0,%1,%2,%3};"
        : "+f"(d[0]), "+f"(d[1]), "+f"(d[2]), "+f"(d[3])
        : "r"(a0), "r"(a1), "r"(a2), "r"(a3), "r"(b0), "r"(b1));
}

// ======================= projection: [16384,1024] @ [1024,64] =======================
#define XPAD 36
__global__ __launch_bounds__(256) void proj_tc(
    const float* __restrict__ q, const float* __restrict__ k, const float* __restrict__ v,
    const float* __restrict__ Wq, const float* __restrict__ Wk, const float* __restrict__ Wv)
{
    __shared__ uint16_t Xh[128][XPAD], Xl[128][XPAD], Wh[64][XPAD], Wl[64][XPAD];
    const int tid = threadIdx.x, wid = tid >> 5, lane = tid & 31;
    const int g = lane >> 2, t4 = lane & 3;
    const int y = blockIdx.y;
    const float* X = (y == 0) ? q : (y == 1) ? k : v;
    const float* W = (y == 0) ? Wq : (y == 1) ? Wk : Wv;
    const int m0 = blockIdx.x * 128;

    float acc[8][4] = {};

    for (int c0 = 0; c0 < DD; c0 += 32) {
        __syncthreads();
        for (int i = tid; i < 1024; i += 256) {
            int r = i >> 3, c4 = (i & 7) << 2;
            float4 xv = *(const float4*)&X[(size_t)(m0 + r) * DD + c0 + c4];
            uint32_t h01 = pack2(xv.x, xv.y), h23 = pack2(xv.z, xv.w);
            float hx = __uint_as_float(h01 << 16), hy = __uint_as_float(h01 & 0xffff0000u);
            float hz = __uint_as_float(h23 << 16), hw = __uint_as_float(h23 & 0xffff0000u);
            uint32_t l01 = pack2(xv.x - hx, xv.y - hy), l23 = pack2(xv.z - hz, xv.w - hw);
            *(uint32_t*)&Xh[r][c4]     = h01; *(uint32_t*)&Xh[r][c4 + 2] = h23;
            *(uint32_t*)&Xl[r][c4]     = l01; *(uint32_t*)&Xl[r][c4 + 2] = l23;
        }
        {
            int n = tid & 63, kb = (tid >> 6) << 3;
            float w[8];
            #pragma unroll
            for (int e = 0; e < 8; e++) w[e] = W[(size_t)(c0 + kb + e) * HH + n];
            #pragma unroll
            for (int e = 0; e < 4; e++) {
                uint32_t hp = pack2(w[2*e], w[2*e+1]);
                float h0 = __uint_as_float(hp << 16), h1 = __uint_as_float(hp & 0xffff0000u);
                uint32_t lp = pack2(w[2*e] - h0, w[2*e+1] - h1);
                *(uint32_t*)&Wh[n][kb + 2*e] = hp;
                *(uint32_t*)&Wl[n][kb + 2*e] = lp;
            }
        }
        __syncthreads();
        const int row = (wid << 4) + g;
        #pragma unroll
        for (int cs = 0; cs < 2; cs++) {
            const int kc = cs * 16 + 2 * t4;
            uint32_t ah0 = *(uint32_t*)&Xh[row][kc],     ah1 = *(uint32_t*)&Xh[row + 8][kc];
            uint32_t ah2 = *(uint32_t*)&Xh[row][kc + 8], ah3 = *(uint32_t*)&Xh[row + 8][kc + 8];
            uint32_t al0 = *(uint32_t*)&Xl[row][kc],     al1 = *(uint32_t*)&Xl[row + 8][kc];
            uint32_t al2 = *(uint32_t*)&Xl[row][kc + 8], al3 = *(uint32_t*)&Xl[row + 8][kc + 8];
            #pragma unroll
            for (int j = 0; j < 8; j++) {
                int n = 8 * j + g;
                uint32_t bh0 = *(uint32_t*)&Wh[n][kc], bh1 = *(uint32_t*)&Wh[n][kc + 8];
                uint32_t bl0 = *(uint32_t*)&Wl[n][kc], bl1 = *(uint32_t*)&Wl[n][kc + 8];
                mma16816(acc[j], ah0, ah1, ah2, ah3, bh0, bh1);
                mma16816(acc[j], ah0, ah1, ah2, ah3, bl0, bl1);
                mma16816(acc[j], al0, al1, al2, al3, bh0, bh1);
            }
        }
    }

    const int row0 = m0 + (wid << 4) + g;
    if (y < 2) {
        __nv_bfloat16* Oh = (y == 0) ? g_qh_hi : g_kh_hi;
        __nv_bfloat16* Ol = (y == 0) ? g_qh_lo : g_kh_lo;
        #pragma unroll
        for (int j = 0; j < 8; j++) {
            int col = 8 * j + 2 * t4;
            uint32_t hp0 = pack2(acc[j][0], acc[j][1]);
            float h0 = __uint_as_float(hp0 << 16), h1 = __uint_as_float(hp0 & 0xffff0000u);
            uint32_t lp0 = pack2(acc[j][0] - h0, acc[j][1] - h1);
            *(uint32_t*)&Oh[(size_t)row0 * HH + col] = hp0;
            *(uint32_t*)&Ol[(size_t)row0 * HH + col] = lp0;
            uint32_t hp1 = pack2(acc[j][2], acc[j][3]);
            float h2 = __uint_as_float(hp1 << 16), h3 = __uint_as_float(hp1 & 0xffff0000u);
            uint32_t lp1 = pack2(acc[j][2] - h2, acc[j][3] - h3);
            *(uint32_t*)&Oh[(size_t)(row0 + 8) * HH + col] = hp1;
            *(uint32_t*)&Ol[(size_t)(row0 + 8) * HH + col] = lp1;
        }
    } else {
        #pragma unroll
        for (int j = 0; j < 8; j++) {
            int h = 8 * j + 2 * t4;
            #pragma unroll
            for (int e = 0; e < 4; e++) {
                int hc = h + (e & 1);
                int rr = row0 + ((e >= 2) ? 8 : 0);
                float val = acc[j][e];
                __nv_bfloat16 bh = __float2bfloat16(val);
                float res = val - __bfloat162float(bh);
                g_vt_hi[(size_t)hc * NT + rr] = bh;
                g_vt_lo[(size_t)hc * NT + rr] = __float2bfloat16(res);
            }
        }
    }
}

// ======================= flash attention: split-KV halves, BM=128, BN=64 =======================
// smem: Qh[128][68] @0, Ql @8704, Kh[64][68] @17408, Kl @21760, Vh @26112, Vl @30464 -> 69632 bytes
__global__ __launch_bounds__(256, 1) void attn_tc()
{
    extern __shared__ uint16_t sm[];
    uint16_t* Qh = sm;            uint16_t* Ql = sm + 8704;
    uint16_t* Kh = sm + 17408;    uint16_t* Kl = sm + 21760;
    uint16_t* Vh = sm + 26112;    uint16_t* Vl = sm + 30464;
    const int tid = threadIdx.x, wid = tid >> 5, lane = tid & 31;
    const int g = lane >> 2, t4 = lane & 3;
    const int b = blockIdx.y;
    // longest-first: bid.x 0,1 -> qb=NQB-1 (two halves), etc.
    const int qb = (NQB - 1) - (blockIdx.x >> 1);
    const int half = blockIdx.x & 1;
    const int q0 = qb * 128, bT = b * TT;
    const int rowA = (wid << 4) + g;
    // tile range: half0 = [0, qb+1), half1 = [qb+1, 2qb+2)  (equal lengths)
    const int tstart = half ? (qb + 1) : 0;
    const int tend   = half ? (2 * qb + 2) : (qb + 1);

    for (int i = tid; i < 2048; i += 256) {
        int r = i >> 4, c4 = (i & 15) << 2;
        *(uint2*)&Qh[r * 68 + c4] = *(const uint2*)&g_qh_hi[(size_t)(bT + q0 + r) * HH + c4];
        *(uint2*)&Ql[r * 68 + c4] = *(const uint2*)&g_qh_lo[(size_t)(bT + q0 + r) * HH + c4];
    }

    float oacc[8][4] = {};
    // finite floor (NOT -inf): keeps corr/exp finite when the first tiles of a
    // row's range are fully causally masked (the R5 NaN bug).
    float m0r = MFLOOR, m1r = MFLOOR, l0r = 0.0f, l1r = 0.0f;

    for (int tt = tstart; tt < tend; tt++) {
        const int k0 = tt * 64;
        __syncthreads();
        for (int i = tid; i < 1024; i += 256) {
            int r = i >> 4, c4 = (i & 15) << 2;
            *(uint2*)&Kh[r * 68 + c4] = *(const uint2*)&g_kh_hi[(size_t)(bT + k0 + r) * HH + c4];
            *(uint2*)&Kl[r * 68 + c4] = *(const uint2*)&g_kh_lo[(size_t)(bT + k0 + r) * HH + c4];
            *(uint2*)&Vh[r * 68 + c4] = *(const uint2*)&g_vt_hi[(size_t)r * NT + bT + k0 + c4];
            *(uint2*)&Vl[r * 68 + c4] = *(const uint2*)&g_vt_lo[(size_t)r * NT + bT + k0 + c4];
        }
        __syncthreads();

        // S = Q K^T (3 split terms)
        float sacc[8][4] = {};
        #pragma unroll
        for (int c = 0; c < 4; c++) {
            const int kc = 16 * c + 2 * t4;
            uint32_t ah0 = *(uint32_t*)&Qh[rowA * 68 + kc],       ah1 = *(uint32_t*)&Qh[(rowA + 8) * 68 + kc];
            uint32_t ah2 = *(uint32_t*)&Qh[rowA * 68 + kc + 8],   ah3 = *(uint32_t*)&Qh[(rowA + 8) * 68 + kc + 8];
            uint32_t al0 = *(uint32_t*)&Ql[rowA * 68 + kc],       al1 = *(uint32_t*)&Ql[(rowA + 8) * 68 + kc];
            uint32_t al2 = *(uint32_t*)&Ql[rowA * 68 + kc + 8],   al3 = *(uint32_t*)&Ql[(rowA + 8) * 68 + kc + 8];
            #pragma unroll
            for (int j = 0; j < 8; j++) {
                int n = 8 * j + g;
                uint32_t bh0 = *(uint32_t*)&Kh[n * 68 + kc], bh1 = *(uint32_t*)&Kh[n * 68 + kc + 8];
                uint32_t bl0 = *(uint32_t*)&Kl[n * 68 + kc], bl1 = *(uint32_t*)&Kl[n * 68 + kc + 8];
                mma16816(sacc[j], ah0, ah1, ah2, ah3, bh0, bh1);
                mma16816(sacc[j], ah0, ah1, ah2, ah3, bl0, bl1);
                mma16816(sacc[j], al0, al1, al2, al3, bh0, bh1);
            }
        }

        // scale + causal mask: tile tt touches the diagonal iff tt >= 2*qb
        const bool domask = (tt >= 2 * qb);
        #pragma unroll
        for (int j = 0; j < 8; j++) {
            int col = k0 + 8 * j + 2 * t4;
            #pragma unroll
            for (int e = 0; e < 4; e++) {
                float val = sacc[j][e] * 0.125f;
                if (domask) {
                    int rr = q0 + rowA + ((e >= 2) ? 8 : 0);
                    if (col + (e & 1) > rr) val = NEGINF;
                }
                sacc[j][e] = val;
            }
        }

        // online softmax (all state finite: m >= MFLOOR)
        float mx0 = NEGINF, mx1 = NEGINF;
        #pragma unroll
        for (int j = 0; j < 8; j++) {
            mx0 = fmaxf(mx0, fmaxf(sacc[j][0], sacc[j][1]));
            mx1 = fmaxf(mx1, fmaxf(sacc[j][2], sacc[j][3]));
        }
        mx0 = fmaxf(mx0, __shfl_xor_sync(0xffffffffu, mx0, 1));
        mx0 = fmaxf(mx0, __shfl_xor_sync(0xffffffffu, mx0, 2));
        mx1 = fmaxf(mx1, __shfl_xor_sync(0xffffffffu, mx1, 1));
        mx1 = fmaxf(mx1, __shfl_xor_sync(0xffffffffu, mx1, 2));
        const float mn0 = fmaxf(m0r, mx0), mn1 = fmaxf(m1r, mx1);   // >= MFLOOR, finite
        const float corr0 = __expf(m0r - mn0), corr1 = __expf(m1r - mn1);
        float s0 = 0.0f, s1 = 0.0f;
        #pragma unroll
        for (int j = 0; j < 8; j++) {
            float p0 = __expf(sacc[j][0] - mn0), p1 = __expf(sacc[j][1] - mn0);
            float p2 = __expf(sacc[j][2] - mn1), p3 = __expf(sacc[j][3] - mn1);
            sacc[j][0] = p0; sacc[j][1] = p1; sacc[j][2] = p2; sacc[j][3] = p3;
            s0 += p0 + p1; s1 += p2 + p3;
        }
        s0 += __shfl_xor_sync(0xffffffffu, s0, 1);
        s0 += __shfl_xor_sync(0xffffffffu, s0, 2);
        s1 += __shfl_xor_sync(0xffffffffu, s1, 1);
        s1 += __shfl_xor_sync(0xffffffffu, s1, 2);
        l0r = l0r * corr0 + s0; l1r = l1r * corr1 + s1;
        m0r = mn0; m1r = mn1;

        #pragma unroll
        for (int j = 0; j < 8; j++) {
            oacc[j][0] *= corr0; oacc[j][1] *= corr0;
            oacc[j][2] *= corr1; oacc[j][3] *= corr1;
        }

        // O += P V (P in registers)
        #pragma unroll
        for (int c = 0; c < 4; c++) {
            uint32_t ph0 = pack2(sacc[2*c][0],   sacc[2*c][1]);
            uint32_t ph1 = pack2(sacc[2*c][2],   sacc[2*c][3]);
            uint32_t ph2 = pack2(sacc[2*c+1][0], sacc[2*c+1][1]);
            uint32_t ph3 = pack2(sacc[2*c+1][2], sacc[2*c+1][3]);
            float r0 = sacc[2*c][0]   - __uint_as_float(ph0 << 16);
            float r1 = sacc[2*c][1]   - __uint_as_float(ph0 & 0xffff0000u);
            float r2 = sacc[2*c][2]   - __uint_as_float(ph1 << 16);
            float r3 = sacc[2*c][3]   - __uint_as_float(ph1 & 0xffff0000u);
            float r4 = sacc[2*c+1][0] - __uint_as_float(ph2 << 16);
            float r5 = sacc[2*c+1][1] - __uint_as_float(ph2 & 0xffff0000u);
            float r6 = sacc[2*c+1][2] - __uint_as_float(ph3 << 16);
            float r7 = sacc[2*c+1][3] - __uint_as_float(ph3 & 0xffff0000u);
            uint32_t pl0 = pack2(r0, r1), pl1 = pack2(r2, r3);
            uint32_t pl2 = pack2(r4, r5), pl3 = pack2(r6, r7);
            const int kc = 16 * c + 2 * t4;
            #pragma unroll
            for (int j2 = 0; j2 < 8; j2++) {
                int n = 8 * j2 + g;
                uint32_t bh0 = *(uint32_t*)&Vh[n * 68 + kc], bh1 = *(uint32_t*)&Vh[n * 68 + kc + 8];
                uint32_t bl0 = *(uint32_t*)&Vl[n * 68 + kc], bl1 = *(uint32_t*)&Vl[n * 68 + kc + 8];
                mma16816(oacc[j2], ph0, ph1, ph2, ph3, bh0, bh1);
                mma16816(oacc[j2], ph0, ph1, ph2, ph3, bl0, bl1);
                mma16816(oacc[j2], pl0, pl1, pl2, pl3, bh0, bh1);
            }
        }
    }

    // store partials (unnormalized O, m, l)
    float* po = g_po[half];
    #pragma unroll
    for (int j = 0; j < 8; j++) {
        int col = 8 * j + 2 * t4;
        *(float2*)&po[(size_t)(bT + q0 + rowA) * HH + col] = make_float2(oacc[j][0], oacc[j][1]);
        *(float2*)&po[(size_t)(bT + q0 + rowA + 8) * HH + col] = make_float2(oacc[j][2], oacc[j][3]);
    }
    if (t4 == 0) {
        g_pm[half][bT + q0 + rowA] = m0r;      g_pl[half][bT + q0 + rowA] = l0r;
        g_pm[half][bT + q0 + rowA + 8] = m1r;  g_pl[half][bT + q0 + rowA + 8] = l1r;
    }
}

// ======================= merge the two split-KV partials =======================
__global__ __launch_bounds__(256) void merge_k(float* __restrict__ out)
{
    const int idx = blockIdx.x * 256 + threadIdx.x;       // float4 index
    const int row = idx >> 4;
    const int c4 = (idx & 15) << 2;
    const float m0 = g_pm[0][row], m1 = g_pm[1][row];
    const float ms = fmaxf(m0, m1);          // finite: m >= MFLOOR
    const float w0 = __expf(m0 - ms), w1 = __expf(m1 - ms);
    const float inv = 1.0f / (g_pl[0][row] * w0 + g_pl[1][row] * w1);
    const float4 a = *(const float4*)&g_po[0][(size_t)row * HH + c4];
    const float4 bq = *(const float4*)&g_po[1][(size_t)row * HH + c4];
    *(float4*)&out[(size_t)row * HH + c4] = make_float4(
        (a.x * w0 + bq.x * w1) * inv, (a.y * w0 + bq.y * w1) * inv,
        (a.z * w0 + bq.z * w1) * inv, (a.w * w0 + bq.w * w1) * inv);
}

extern "C" void kernel_launch(void* const* d_in, const int* in_sizes, int n_in,
                              void* d_out, int out_size)
{
    const float* q  = (const float*)d_in[0];
    const float* k  = (const float*)d_in[1];
    const float* v  = (const float*)d_in[2];
    const float* Wq = (const float*)d_in[3];
    const float* Wk = (const float*)d_in[4];
    const float* Wv = (const float*)d_in[5];
    // d_in[6] (tril mask) implemented analytically

    proj_tc<<<dim3(NT / 128, 3), 256>>>(q, k, v, Wq, Wk, Wv);

    const int attn_smem = 69632;
    cudaFuncSetAttribute(attn_tc, cudaFuncAttributeMaxDynamicSharedMemorySize, attn_smem);
    attn_tc<<<dim3(2 * NQB, BB), 256, attn_smem>>>();

    merge_k<<<(NT * HH / 4) / 256, 256>>>((float*)d_out);
}

// round 8
// speedup vs baseline: 2.1152x; 1.1919x over previous
#include <cuda_runtime.h>
#include <cuda_bf16.h>
#include <cstdint>

#define BB 4
#define TT 4096
#define DD 1024
#define HH 64
#define NT (BB*TT)
#define NQB (TT/128)

#define NEGINF __int_as_float(0xff800000)
#define MFLOOR (-1e30f)

// bf16 hi/lo projected tensors (12 MB static scratch)
__device__ __nv_bfloat16 g_qh_hi[NT*HH], g_qh_lo[NT*HH];
__device__ __nv_bfloat16 g_kh_hi[NT*HH], g_kh_lo[NT*HH];
__device__ __nv_bfloat16 g_vt_hi[HH*NT], g_vt_lo[HH*NT];   // V transposed: [h][token]

// pre-converted weights, transposed [n][k] bf16 hi/lo
__device__ __nv_bfloat16 g_wt_hi[3][HH*DD], g_wt_lo[3][HH*DD];

// split-KV partials: unnormalized O + running max/sum per row
__device__ float g_po[2][NT*HH];
__device__ float g_pm[2][NT];
__device__ float g_pl[2][NT];

// pack two floats -> bf16x2 (lo arg in low half, hi arg in high half)
__device__ __forceinline__ uint32_t pack2(float lo, float hi) {
    uint32_t r;
    asm("cvt.rn.bf16x2.f32 %0, %1, %2;" : "=r"(r) : "f"(hi), "f"(lo));
    return r;
}
__device__ __forceinline__ void mma16816(float* d, uint32_t a0, uint32_t a1, uint32_t a2, uint32_t a3,
                                         uint32_t b0, uint32_t b1) {
    asm volatile("mma.sync.aligned.m16n8k16.row.col.f32.bf16.bf16.f32 "
        "{%0,%1,%2,%3}, {%4,%5,%6,%7}, {%8,%9}, {%0,%1,%2,%3};"
        : "+f"(d[0]), "+f"(d[1]), "+f"(d[2]), "+f"(d[3])
        : "r"(a0), "r"(a1), "r"(a2), "r"(a3), "r"(b0), "r"(b1));
}

// ======================= W pre-conversion: [1024,64] -> [64][1024] bf16 hi/lo =======================
__global__ __launch_bounds__(256) void wconv_k(
    const float* __restrict__ Wq, const float* __restrict__ Wk, const float* __restrict__ Wv)
{
    const int gid = blockIdx.x * 256 + threadIdx.x;   // 3*64*1024 = 196608 threads
    const int y = gid >> 16;
    const int rem = gid & 65535;
    const int n = rem >> 10, k = rem & 1023;
    const float* W = (y == 0) ? Wq : (y == 1) ? Wk : Wv;
    float w = W[(size_t)k * HH + n];
    __nv_bfloat16 bh = __float2bfloat16(w);
    g_wt_hi[y][(size_t)n * DD + k] = bh;
    g_wt_lo[y][(size_t)n * DD + k] = __float2bfloat16(w - __bfloat162float(bh));
}

// ======================= projection: [16384,1024] @ [1024,64], K-chunk 64, double-buffered =======================
// dynamic smem (uint16): Xh0@0(8704) Xl0@8704 Wh0@17408(4352) Wl0@21760 | Xh1@26112 Xl1@34816 Wh1@43520 Wl1@47872
// total 52224 u16 = 104448 B
__global__ __launch_bounds__(256) void proj_tc(
    const float* __restrict__ q, const float* __restrict__ k, const float* __restrict__ v)
{
    extern __shared__ uint16_t psm[];
    uint16_t* Xhb[2] = {psm,         psm + 26112};
    uint16_t* Xlb[2] = {psm + 8704,  psm + 34816};
    uint16_t* Whb[2] = {psm + 17408, psm + 43520};
    uint16_t* Wlb[2] = {psm + 21760, psm + 47872};

    const int tid = threadIdx.x, wid = tid >> 5, lane = tid & 31;
    const int g = lane >> 2, t4 = lane & 3;
    const int y = blockIdx.y;
    const float* X = (y == 0) ? q : (y == 1) ? k : v;
    const __nv_bfloat16* gwh = g_wt_hi[y];
    const __nv_bfloat16* gwl = g_wt_lo[y];
    const int m0 = blockIdx.x * 128;
    const int rowA = (wid << 4) + g;

    float4 xv[8];
    uint4 wh4[2], wl4[2];

    // --- prefetch chunk c0 into registers ---
    auto load_regs = [&](int c0) {
        #pragma unroll
        for (int e = 0; e < 8; e++) {
            int idx = tid + 256 * e, r = idx >> 4, c4 = (idx & 15) << 2;
            xv[e] = *(const float4*)&X[(size_t)(m0 + r) * DD + c0 + c4];
        }
        #pragma unroll
        for (int e = 0; e < 2; e++) {
            int idx = tid + 256 * e, n = idx >> 3, k8 = (idx & 7) << 3;
            wh4[e] = *(const uint4*)&gwh[(size_t)n * DD + c0 + k8];
            wl4[e] = *(const uint4*)&gwl[(size_t)n * DD + c0 + k8];
        }
    };
    // --- convert + store prefetched registers into buffer bb ---
    auto store_chunk = [&](int bb) {
        #pragma unroll
        for (int e = 0; e < 8; e++) {
            int idx = tid + 256 * e, r = idx >> 4, c4 = (idx & 15) << 2;
            float4 x = xv[e];
            uint32_t h01 = pack2(x.x, x.y), h23 = pack2(x.z, x.w);
            float hx = __uint_as_float(h01 << 16), hy = __uint_as_float(h01 & 0xffff0000u);
            float hz = __uint_as_float(h23 << 16), hw = __uint_as_float(h23 & 0xffff0000u);
            uint32_t l01 = pack2(x.x - hx, x.y - hy), l23 = pack2(x.z - hz, x.w - hw);
            *(uint32_t*)&Xhb[bb][r * 68 + c4]     = h01;
            *(uint32_t*)&Xhb[bb][r * 68 + c4 + 2] = h23;
            *(uint32_t*)&Xlb[bb][r * 68 + c4]     = l01;
            *(uint32_t*)&Xlb[bb][r * 68 + c4 + 2] = l23;
        }
        #pragma unroll
        for (int e = 0; e < 2; e++) {
            int idx = tid + 256 * e, n = idx >> 3, k8 = (idx & 7) << 3;
            const uint32_t* sh = (const uint32_t*)&wh4[e];
            const uint32_t* sl = (const uint32_t*)&wl4[e];
            #pragma unroll
            for (int u = 0; u < 4; u++) {
                *(uint32_t*)&Whb[bb][n * 68 + k8 + 2 * u] = sh[u];
                *(uint32_t*)&Wlb[bb][n * 68 + k8 + 2 * u] = sl[u];
            }
        }
    };

    float acc[8][4] = {};

    load_regs(0);
    store_chunk(0);
    __syncthreads();

    for (int c = 0; c < 16; c++) {
        const int cur = c & 1, nxt = cur ^ 1;
        const bool more = (c + 1 < 16);
        if (more) load_regs((c + 1) * 64);   // global loads in flight during MMAs

        uint16_t* Xh = Xhb[cur]; uint16_t* Xl = Xlb[cur];
        uint16_t* Wh = Whb[cur]; uint16_t* Wl = Wlb[cur];
        #pragma unroll
        for (int cs = 0; cs < 4; cs++) {
            const int kc = cs * 16 + 2 * t4;
            uint32_t ah0 = *(uint32_t*)&Xh[rowA * 68 + kc],       ah1 = *(uint32_t*)&Xh[(rowA + 8) * 68 + kc];
            uint32_t ah2 = *(uint32_t*)&Xh[rowA * 68 + kc + 8],   ah3 = *(uint32_t*)&Xh[(rowA + 8) * 68 + kc + 8];
            uint32_t al0 = *(uint32_t*)&Xl[rowA * 68 + kc],       al1 = *(uint32_t*)&Xl[(rowA + 8) * 68 + kc];
            uint32_t al2 = *(uint32_t*)&Xl[rowA * 68 + kc + 8],   al3 = *(uint32_t*)&Xl[(rowA + 8) * 68 + kc + 8];
            #pragma unroll
            for (int j = 0; j < 8; j++) {
                int n = 8 * j + g;
                uint32_t bh0 = *(uint32_t*)&Wh[n * 68 + kc], bh1 = *(uint32_t*)&Wh[n * 68 + kc + 8];
                uint32_t bl0 = *(uint32_t*)&Wl[n * 68 + kc], bl1 = *(uint32_t*)&Wl[n * 68 + kc + 8];
                mma16816(acc[j], ah0, ah1, ah2, ah3, bh0, bh1);
                mma16816(acc[j], ah0, ah1, ah2, ah3, bl0, bl1);
                mma16816(acc[j], al0, al1, al2, al3, bh0, bh1);
            }
        }
        if (more) store_chunk(nxt);
        __syncthreads();
    }

    const int row0 = m0 + rowA;
    if (y < 2) {
        __nv_bfloat16* Oh = (y == 0) ? g_qh_hi : g_kh_hi;
        __nv_bfloat16* Ol = (y == 0) ? g_qh_lo : g_kh_lo;
        #pragma unroll
        for (int j = 0; j < 8; j++) {
            int col = 8 * j + 2 * t4;
            uint32_t hp0 = pack2(acc[j][0], acc[j][1]);
            float h0 = __uint_as_float(hp0 << 16), h1 = __uint_as_float(hp0 & 0xffff0000u);
            uint32_t lp0 = pack2(acc[j][0] - h0, acc[j][1] - h1);
            *(uint32_t*)&Oh[(size_t)row0 * HH + col] = hp0;
            *(uint32_t*)&Ol[(size_t)row0 * HH + col] = lp0;
            uint32_t hp1 = pack2(acc[j][2], acc[j][3]);
            float h2 = __uint_as_float(hp1 << 16), h3 = __uint_as_float(hp1 & 0xffff0000u);
            uint32_t lp1 = pack2(acc[j][2] - h2, acc[j][3] - h3);
            *(uint32_t*)&Oh[(size_t)(row0 + 8) * HH + col] = hp1;
            *(uint32_t*)&Ol[(size_t)(row0 + 8) * HH + col] = lp1;
        }
    } else {
        // V: stage transposed [h][token] in smem (reuse buffer 0 region; all reads done)
        uint16_t* th = psm;            // 64*128 = 8192
        uint16_t* tl = psm + 8192;
        #pragma unroll
        for (int j = 0; j < 8; j++) {
            int h = 8 * j + 2 * t4;
            #pragma unroll
            for (int e = 0; e < 4; e++) {
                int hc = h + (e & 1);
                int rr = rowA + ((e >= 2) ? 8 : 0);
                float val = acc[j][e];
                __nv_bfloat16 bh = __float2bfloat16(val);
                float res = val - __bfloat162float(bh);
                th[hc * 128 + rr] = __bfloat16_as_ushort(bh);
                tl[hc * 128 + rr] = __bfloat16_as_ushort(__float2bfloat16(res));
            }
        }
        __syncthreads();
        for (int i = tid; i < 1024; i += 256) {
            int h = i >> 4, c2 = i & 15;
            ((uint4*)(&g_vt_hi[(size_t)h * NT + m0]))[c2] = ((const uint4*)th)[h * 16 + c2];
            ((uint4*)(&g_vt_lo[(size_t)h * NT + m0]))[c2] = ((const uint4*)tl)[h * 16 + c2];
        }
    }
}

// ======================= flash attention: split-KV halves, double-buffered K/V =======================
// dynamic smem (uint16): Qh@0(8704) Ql@8704 | buf0@17408: Kh(4352) Kl Vh Vl | buf1@34816 ; total 104448 B
__global__ __launch_bounds__(256, 1) void attn_tc()
{
    extern __shared__ uint16_t sm[];
    uint16_t* Qh = sm;
    uint16_t* Ql = sm + 8704;
    const int tid = threadIdx.x, wid = tid >> 5, lane = tid & 31;
    const int g = lane >> 2, t4 = lane & 3;
    const int b = blockIdx.y;
    const int qb = (NQB - 1) - (blockIdx.x >> 1);   // longest-first
    const int half = blockIdx.x & 1;
    const int q0 = qb * 128, bT = b * TT;
    const int rowA = (wid << 4) + g;
    const int tstart = half ? (qb + 1) : 0;
    const int tend   = half ? (2 * qb + 2) : (qb + 1);

    for (int i = tid; i < 2048; i += 256) {
        int r = i >> 4, c4 = (i & 15) << 2;
        *(uint2*)&Qh[r * 68 + c4] = *(const uint2*)&g_qh_hi[(size_t)(bT + q0 + r) * HH + c4];
        *(uint2*)&Ql[r * 68 + c4] = *(const uint2*)&g_qh_lo[(size_t)(bT + q0 + r) * HH + c4];
    }

    uint2 pkh[4], pkl[4], pvh[4], pvl[4];
    auto load_tile_regs = [&](int k0n) {
        #pragma unroll
        for (int e = 0; e < 4; e++) {
            int idx = tid + 256 * e, r = idx >> 4, c4 = (idx & 15) << 2;
            pkh[e] = *(const uint2*)&g_kh_hi[(size_t)(bT + k0n + r) * HH + c4];
            pkl[e] = *(const uint2*)&g_kh_lo[(size_t)(bT + k0n + r) * HH + c4];
            pvh[e] = *(const uint2*)&g_vt_hi[(size_t)r * NT + bT + k0n + c4];
            pvl[e] = *(const uint2*)&g_vt_lo[(size_t)r * NT + bT + k0n + c4];
        }
    };
    auto store_tile = [&](int bb) {
        uint16_t* base = sm + 17408 + bb * 17408;
        #pragma unroll
        for (int e = 0; e < 4; e++) {
            int idx = tid + 256 * e, r = idx >> 4, c4 = (idx & 15) << 2;
            *(uint2*)&base[r * 68 + c4]          = pkh[e];
            *(uint2*)&base[4352 + r * 68 + c4]   = pkl[e];
            *(uint2*)&base[8704 + r * 68 + c4]   = pvh[e];
            *(uint2*)&base[13056 + r * 68 + c4]  = pvl[e];
        }
    };

    float oacc[8][4] = {};
    float m0r = MFLOOR, m1r = MFLOOR, l0r = 0.0f, l1r = 0.0f;

    load_tile_regs(tstart * 64);
    store_tile(0);
    __syncthreads();

    for (int tt = tstart; tt < tend; tt++) {
        const int k0 = tt * 64;
        const int cur = (tt - tstart) & 1, nxt = cur ^ 1;
        const bool more = (tt + 1 < tend);
        if (more) load_tile_regs((tt + 1) * 64);   // globals in flight during compute

        uint16_t* Kh = sm + 17408 + cur * 17408;
        uint16_t* Kl = Kh + 4352;
        uint16_t* Vh = Kh + 8704;
        uint16_t* Vl = Kh + 13056;

        // S = Q K^T (3 split terms)
        float sacc[8][4] = {};
        #pragma unroll
        for (int c = 0; c < 4; c++) {
            const int kc = 16 * c + 2 * t4;
            uint32_t ah0 = *(uint32_t*)&Qh[rowA * 68 + kc],       ah1 = *(uint32_t*)&Qh[(rowA + 8) * 68 + kc];
            uint32_t ah2 = *(uint32_t*)&Qh[rowA * 68 + kc + 8],   ah3 = *(uint32_t*)&Qh[(rowA + 8) * 68 + kc + 8];
            uint32_t al0 = *(uint32_t*)&Ql[rowA * 68 + kc],       al1 = *(uint32_t*)&Ql[(rowA + 8) * 68 + kc];
            uint32_t al2 = *(uint32_t*)&Ql[rowA * 68 + kc + 8],   al3 = *(uint32_t*)&Ql[(rowA + 8) * 68 + kc + 8];
            #pragma unroll
            for (int j = 0; j < 8; j++) {
                int n = 8 * j + g;
                uint32_t bh0 = *(uint32_t*)&Kh[n * 68 + kc], bh1 = *(uint32_t*)&Kh[n * 68 + kc + 8];
                uint32_t bl0 = *(uint32_t*)&Kl[n * 68 + kc], bl1 = *(uint32_t*)&Kl[n * 68 + kc + 8];
                mma16816(sacc[j], ah0, ah1, ah2, ah3, bh0, bh1);
                mma16816(sacc[j], ah0, ah1, ah2, ah3, bl0, bl1);
                mma16816(sacc[j], al0, al1, al2, al3, bh0, bh1);
            }
        }

        // scale + causal mask: tile tt touches the diagonal iff tt >= 2*qb
        const bool domask = (tt >= 2 * qb);
        #pragma unroll
        for (int j = 0; j < 8; j++) {
            int col = k0 + 8 * j + 2 * t4;
            #pragma unroll
            for (int e = 0; e < 4; e++) {
                float val = sacc[j][e] * 0.125f;
                if (domask) {
                    int rr = q0 + rowA + ((e >= 2) ? 8 : 0);
                    if (col + (e & 1) > rr) val = NEGINF;
                }
                sacc[j][e] = val;
            }
        }

        // online softmax (state floored at MFLOOR: finite even for fully-masked tiles)
        float mx0 = NEGINF, mx1 = NEGINF;
        #pragma unroll
        for (int j = 0; j < 8; j++) {
            mx0 = fmaxf(mx0, fmaxf(sacc[j][0], sacc[j][1]));
            mx1 = fmaxf(mx1, fmaxf(sacc[j][2], sacc[j][3]));
        }
        mx0 = fmaxf(mx0, __shfl_xor_sync(0xffffffffu, mx0, 1));
        mx0 = fmaxf(mx0, __shfl_xor_sync(0xffffffffu, mx0, 2));
        mx1 = fmaxf(mx1, __shfl_xor_sync(0xffffffffu, mx1, 1));
        mx1 = fmaxf(mx1, __shfl_xor_sync(0xffffffffu, mx1, 2));
        const float mn0 = fmaxf(m0r, mx0), mn1 = fmaxf(m1r, mx1);
        const float corr0 = __expf(m0r - mn0), corr1 = __expf(m1r - mn1);
        float s0 = 0.0f, s1 = 0.0f;
        #pragma unroll
        for (int j = 0; j < 8; j++) {
            float p0 = __expf(sacc[j][0] - mn0), p1 = __expf(sacc[j][1] - mn0);
            float p2 = __expf(sacc[j][2] - mn1), p3 = __expf(sacc[j][3] - mn1);
            sacc[j][0] = p0; sacc[j][1] = p1; sacc[j][2] = p2; sacc[j][3] = p3;
            s0 += p0 + p1; s1 += p2 + p3;
        }
        s0 += __shfl_xor_sync(0xffffffffu, s0, 1);
        s0 += __shfl_xor_sync(0xffffffffu, s0, 2);
        s1 += __shfl_xor_sync(0xffffffffu, s1, 1);
        s1 += __shfl_xor_sync(0xffffffffu, s1, 2);
        l0r = l0r * corr0 + s0; l1r = l1r * corr1 + s1;
        m0r = mn0; m1r = mn1;

        #pragma unroll
        for (int j = 0; j < 8; j++) {
            oacc[j][0] *= corr0; oacc[j][1] *= corr0;
            oacc[j][2] *= corr1; oacc[j][3] *= corr1;
        }

        // O += P V (P in registers)
        #pragma unroll
        for (int c = 0; c < 4; c++) {
            uint32_t ph0 = pack2(sacc[2*c][0],   sacc[2*c][1]);
            uint32_t ph1 = pack2(sacc[2*c][2],   sacc[2*c][3]);
            uint32_t ph2 = pack2(sacc[2*c+1][0], sacc[2*c+1][1]);
            uint32_t ph3 = pack2(sacc[2*c+1][2], sacc[2*c+1][3]);
            float r0 = sacc[2*c][0]   - __uint_as_float(ph0 << 16);
            float r1 = sacc[2*c][1]   - __uint_as_float(ph0 & 0xffff0000u);
            float r2 = sacc[2*c][2]   - __uint_as_float(ph1 << 16);
            float r3 = sacc[2*c][3]   - __uint_as_float(ph1 & 0xffff0000u);
            float r4 = sacc[2*c+1][0] - __uint_as_float(ph2 << 16);
            float r5 = sacc[2*c+1][1] - __uint_as_float(ph2 & 0xffff0000u);
            float r6 = sacc[2*c+1][2] - __uint_as_float(ph3 << 16);
            float r7 = sacc[2*c+1][3] - __uint_as_float(ph3 & 0xffff0000u);
            uint32_t pl0 = pack2(r0, r1), pl1 = pack2(r2, r3);
            uint32_t pl2 = pack2(r4, r5), pl3 = pack2(r6, r7);
            const int kc = 16 * c + 2 * t4;
            #pragma unroll
            for (int j2 = 0; j2 < 8; j2++) {
                int n = 8 * j2 + g;
                uint32_t bh0 = *(uint32_t*)&Vh[n * 68 + kc], bh1 = *(uint32_t*)&Vh[n * 68 + kc + 8];
                uint32_t bl0 = *(uint32_t*)&Vl[n * 68 + kc], bl1 = *(uint32_t*)&Vl[n * 68 + kc + 8];
                mma16816(oacc[j2], ph0, ph1, ph2, ph3, bh0, bh1);
                mma16816(oacc[j2], ph0, ph1, ph2, ph3, bl0, bl1);
                mma16816(oacc[j2], pl0, pl1, pl2, pl3, bh0, bh1);
            }
        }

        if (more) store_tile(nxt);
        __syncthreads();
    }

    // store partials (unnormalized O, m, l)
    float* po = g_po[half];
    #pragma unroll
    for (int j = 0; j < 8; j++) {
        int col = 8 * j + 2 * t4;
        *(float2*)&po[(size_t)(bT + q0 + rowA) * HH + col] = make_float2(oacc[j][0], oacc[j][1]);
        *(float2*)&po[(size_t)(bT + q0 + rowA + 8) * HH + col] = make_float2(oacc[j][2], oacc[j][3]);
    }
    if (t4 == 0) {
        g_pm[half][bT + q0 + rowA] = m0r;      g_pl[half][bT + q0 + rowA] = l0r;
        g_pm[half][bT + q0 + rowA + 8] = m1r;  g_pl[half][bT + q0 + rowA + 8] = l1r;
    }
}

// ======================= merge the two split-KV partials =======================
__global__ __launch_bounds__(256) void merge_k(float* __restrict__ out)
{
    const int idx = blockIdx.x * 256 + threadIdx.x;
    const int row = idx >> 4;
    const int c4 = (idx & 15) << 2;
    const float m0 = g_pm[0][row], m1 = g_pm[1][row];
    const float ms = fmaxf(m0, m1);
    const float w0 = __expf(m0 - ms), w1 = __expf(m1 - ms);
    const float inv = 1.0f / (g_pl[0][row] * w0 + g_pl[1][row] * w1);
    const float4 a = *(const float4*)&g_po[0][(size_t)row * HH + c4];
    const float4 bq = *(const float4*)&g_po[1][(size_t)row * HH + c4];
    *(float4*)&out[(size_t)row * HH + c4] = make_float4(
        (a.x * w0 + bq.x * w1) * inv, (a.y * w0 + bq.y * w1) * inv,
        (a.z * w0 + bq.z * w1) * inv, (a.w * w0 + bq.w * w1) * inv);
}

extern "C" void kernel_launch(void* const* d_in, const int* in_sizes, int n_in,
                              void* d_out, int out_size)
{
    const float* q  = (const float*)d_in[0];
    const float* k  = (const float*)d_in[1];
    const float* v  = (const float*)d_in[2];
    const float* Wq = (const float*)d_in[3];
    const float* Wk = (const float*)d_in[4];
    const float* Wv = (const float*)d_in[5];
    // d_in[6] (tril mask) implemented analytically

    wconv_k<<<768, 256>>>(Wq, Wk, Wv);

    const int proj_smem = 104448;
    cudaFuncSetAttribute(proj_tc, cudaFuncAttributeMaxDynamicSharedMemorySize, proj_smem);
    proj_tc<<<dim3(NT / 128, 3), 256, proj_smem>>>(q, k, v);

    const int attn_smem = 104448;
    cudaFuncSetAttribute(attn_tc, cudaFuncAttributeMaxDynamicSharedMemorySize, attn_smem);
    attn_tc<<<dim3(2 * NQB, BB), 256, attn_smem>>>();

    merge_k<<<(NT * HH / 4) / 256, 256>>>((float*)d_out);
}